// round 2
// baseline (speedup 1.0000x reference)
#include <cuda_runtime.h>
#include <cstdint>

#define NPTS 16384
#define BATCH 16
#define INC 7

// ---------------- scratch (device globals; no allocs allowed) ----------------
__device__ float              g_h4[(size_t)BATCH * 128 * NPTS]; // 128 MB, (b, c, i)
__device__ unsigned char      g_gid[BATCH * NPTS];
__device__ unsigned long long g_pmax[BATCH * 1024];  // packed (valbits<<32)|(~idx)
__device__ unsigned int       g_gmax[4 * 1024];      // float bits, vals >= 0
__device__ float              g_u1[17 * 512];        // rows 0..15 = batches, 16 = group

// ---------------- kernel A: fused 7->64->64->64->128 ----------------
// smem layout (floats):
//  w0:0(448) b0:448(64) w1:512(4096) b1:4608(64) w2:4672(4096) b2:8768(64)
//  w3:8832(8192) b3:17024(128) | hA:17152(16384) hB:33536(16384)
#define KA_SMEM_FLOATS (17152 + 2 * 16384)

__device__ __forceinline__ void smcpy(float* dst, const float* src, int n, int tid) {
    for (int i = tid; i < n; i += 256) dst[i] = src[i];
}

__device__ __forceinline__ void mlp64(const float* __restrict__ sw, const float* __restrict__ sb,
                                      const float* __restrict__ ain, float* __restrict__ aout, int tid) {
#pragma unroll 1
    for (int c0 = 0; c0 < 64; c0 += 8) {
        float acc[8];
#pragma unroll
        for (int u = 0; u < 8; u++) acc[u] = sb[c0 + u];
#pragma unroll 4
        for (int k = 0; k < 64; k += 4) {
            float a0 = ain[(k + 0) * 256 + tid];
            float a1 = ain[(k + 1) * 256 + tid];
            float a2 = ain[(k + 2) * 256 + tid];
            float a3 = ain[(k + 3) * 256 + tid];
#pragma unroll
            for (int u = 0; u < 8; u++) {
                float4 w4 = *reinterpret_cast<const float4*>(&sw[(c0 + u) * 64 + k]);
                acc[u] = fmaf(w4.x, a0, acc[u]);
                acc[u] = fmaf(w4.y, a1, acc[u]);
                acc[u] = fmaf(w4.z, a2, acc[u]);
                acc[u] = fmaf(w4.w, a3, acc[u]);
            }
        }
#pragma unroll
        for (int u = 0; u < 8; u++) aout[(c0 + u) * 256 + tid] = fmaxf(acc[u], 0.0f);
    }
}

__global__ __launch_bounds__(256, 1)
void kA(const float* __restrict__ points,
        const float* __restrict__ wl0, const float* __restrict__ bl0,
        const float* __restrict__ wl1, const float* __restrict__ bl1,
        const float* __restrict__ wl2, const float* __restrict__ bl2,
        const float* __restrict__ wl3, const float* __restrict__ bl3) {
    extern __shared__ float sm[];
    const int tid = threadIdx.x;
    smcpy(sm + 0,     wl0, 448,  tid);
    smcpy(sm + 448,   bl0, 64,   tid);
    smcpy(sm + 512,   wl1, 4096, tid);
    smcpy(sm + 4608,  bl1, 64,   tid);
    smcpy(sm + 4672,  wl2, 4096, tid);
    smcpy(sm + 8768,  bl2, 64,   tid);
    smcpy(sm + 8832,  wl3, 8192, tid);
    smcpy(sm + 17024, bl3, 128,  tid);
    float* hA = sm + 17152;
    float* hB = sm + 17152 + 16384;
    __syncthreads();

    const int p = blockIdx.x * 256 + tid;   // global point id
    const int b = p >> 14;
    const int i = p & (NPTS - 1);
    const float* pt = points + (size_t)b * INC * NPTS + i;
    float x[INC];
#pragma unroll
    for (int c = 0; c < INC; c++) x[c] = pt[(size_t)c * NPTS];

    // group id = first argmax of channels 3..6
    int g = 0; float bv = x[3];
    if (x[4] > bv) { bv = x[4]; g = 1; }
    if (x[5] > bv) { bv = x[5]; g = 2; }
    if (x[6] > bv) { bv = x[6]; g = 3; }
    g_gid[p] = (unsigned char)g;

    // layer 0: 7 -> 64 (into hA)
#pragma unroll 1
    for (int c0 = 0; c0 < 64; c0 += 8) {
        float acc[8];
#pragma unroll
        for (int u = 0; u < 8; u++) {
            const float* wr = &sm[(c0 + u) * 7];
            float s = sm[448 + c0 + u];
#pragma unroll
            for (int k = 0; k < 7; k++) s = fmaf(wr[k], x[k], s);
            acc[u] = s;
        }
#pragma unroll
        for (int u = 0; u < 8; u++) hA[(c0 + u) * 256 + tid] = fmaxf(acc[u], 0.0f);
    }

    mlp64(sm + 512,  sm + 4608, hA, hB, tid);   // layer 1
    mlp64(sm + 4672, sm + 8768, hB, hA, tid);   // layer 2

    // layer 3: 64 -> 128, write straight to gmem (b, c, i) coalesced
    float* op = g_h4 + (size_t)b * 128 * NPTS + i;
    const float* sw3 = sm + 8832;
    const float* sb3 = sm + 17024;
#pragma unroll 1
    for (int c0 = 0; c0 < 128; c0 += 8) {
        float acc[8];
#pragma unroll
        for (int u = 0; u < 8; u++) acc[u] = sb3[c0 + u];
#pragma unroll 4
        for (int k = 0; k < 64; k += 4) {
            float a0 = hA[(k + 0) * 256 + tid];
            float a1 = hA[(k + 1) * 256 + tid];
            float a2 = hA[(k + 2) * 256 + tid];
            float a3 = hA[(k + 3) * 256 + tid];
#pragma unroll
            for (int u = 0; u < 8; u++) {
                float4 w4 = *reinterpret_cast<const float4*>(&sw3[(c0 + u) * 64 + k]);
                acc[u] = fmaf(w4.x, a0, acc[u]);
                acc[u] = fmaf(w4.y, a1, acc[u]);
                acc[u] = fmaf(w4.z, a2, acc[u]);
                acc[u] = fmaf(w4.w, a3, acc[u]);
            }
        }
#pragma unroll
        for (int u = 0; u < 8; u++) op[(size_t)(c0 + u) * NPTS] = fmaxf(acc[u], 0.0f);
    }
}

// ---------------- kernel B: 128 -> 1024 GEMM + fused max/argmax/groupmax ----------------
#define WSTR 132
#define HSTR 132
#define KB_SMEM_FLOATS (128 * WSTR + 128 * HSTR)

__global__ __launch_bounds__(256, 1)
void kB(const float* __restrict__ wl4, const float* __restrict__ bl4) {
    extern __shared__ float sm[];
    float* ws = sm;                 // [c][k], 128 x WSTR
    float* hs = sm + 128 * WSTR;    // [k][p], 128 x HSTR (also reduction scratch)
    __shared__ unsigned char gid_s[128];

    const int tid = threadIdx.x;
    const int tx = tid & 15;        // point column group
    const int ty = tid >> 4;        // channel row group
    const int bid = blockIdx.x;
    const int b  = bid >> 6;
    const int cc = (bid >> 3) & 7;
    const int pb = bid & 7;
    const int c0 = cc * 128;
    const int pbase0 = pb * 2048;

    // load W chunk (1024x128 slice rows c0..c0+127), same layout, padded stride
#pragma unroll
    for (int j = 0; j < 16; j++) {
        int f4 = tid + 256 * j;
        int c = f4 >> 5, kf = (f4 & 31) * 4;
        float4 v = *reinterpret_cast<const float4*>(wl4 + (size_t)(c0 + c) * 128 + kf);
        *reinterpret_cast<float4*>(&ws[c * WSTR + kf]) = v;
    }
    float biasr[8];
#pragma unroll
    for (int u = 0; u < 8; u++) biasr[u] = bl4[c0 + ty * 8 + u];

    unsigned long long pk[8];
    float gm[8][4];
#pragma unroll
    for (int u = 0; u < 8; u++) {
        pk[u] = 0ull;
#pragma unroll
        for (int g = 0; g < 4; g++) gm[u][g] = 0.0f;
    }

#pragma unroll 1
    for (int tile = 0; tile < 16; tile++) {
        __syncthreads();
        const int pbase = pbase0 + tile * 128;
        // load h tile [k][p]
#pragma unroll
        for (int j = 0; j < 16; j++) {
            int f4 = tid + 256 * j;
            int k = f4 >> 5, cf = (f4 & 31) * 4;
            float4 v = *reinterpret_cast<const float4*>(
                g_h4 + ((size_t)b * 128 + k) * NPTS + pbase + cf);
            *reinterpret_cast<float4*>(&hs[k * HSTR + cf]) = v;
        }
        if (tid < 128) gid_s[tid] = g_gid[b * NPTS + pbase + tid];
        __syncthreads();

        float acc[8][8];
#pragma unroll
        for (int u = 0; u < 8; u++)
#pragma unroll
            for (int v = 0; v < 8; v++) acc[u][v] = 0.0f;

#pragma unroll 1
        for (int k = 0; k < 128; k += 4) {
            float wr[8][4];
#pragma unroll
            for (int u = 0; u < 8; u++) {
                float4 t = *reinterpret_cast<const float4*>(&ws[(ty * 8 + u) * WSTR + k]);
                wr[u][0] = t.x; wr[u][1] = t.y; wr[u][2] = t.z; wr[u][3] = t.w;
            }
#pragma unroll
            for (int kk = 0; kk < 4; kk++) {
                float4 h0 = *reinterpret_cast<const float4*>(&hs[(k + kk) * HSTR + tx * 8]);
                float4 h1 = *reinterpret_cast<const float4*>(&hs[(k + kk) * HSTR + tx * 8 + 4]);
                float hv[8] = {h0.x, h0.y, h0.z, h0.w, h1.x, h1.y, h1.z, h1.w};
#pragma unroll
                for (int u = 0; u < 8; u++)
#pragma unroll
                    for (int v = 0; v < 8; v++)
                        acc[u][v] = fmaf(wr[u][kk], hv[v], acc[u][v]);
            }
        }

        // epilogue: bias + relu + running reductions
#pragma unroll
        for (int v = 0; v < 8; v++) {
            const int plocal = tx * 8 + v;
            const int gi = gid_s[plocal];
            const unsigned int pidx = (unsigned int)(pbase + plocal);
            const unsigned long long lowkey = (unsigned long long)(0xFFFFFFFFu - pidx);
#pragma unroll
            for (int u = 0; u < 8; u++) {
                float val = fmaxf(acc[u][v] + biasr[u], 0.0f);
                unsigned long long key =
                    ((unsigned long long)__float_as_uint(val) << 32) | lowkey;
                if (key > pk[u]) pk[u] = key;
#pragma unroll
                for (int g = 0; g < 4; g++)
                    gm[u][g] = fmaxf(gm[u][g], (gi == g) ? val : 0.0f);
            }
        }
    }

    // cross-thread reduce (over tx) via smem scratch, then atomics
    __syncthreads();
    unsigned long long* rpk = reinterpret_cast<unsigned long long*>(hs); // 16 KB
    float* rgm = reinterpret_cast<float*>(rpk + 128 * 16);               // 32 KB
#pragma unroll
    for (int u = 0; u < 8; u++) {
        int c = ty * 8 + u;
        rpk[c * 16 + tx] = pk[u];
#pragma unroll
        for (int g = 0; g < 4; g++) rgm[(c * 16 + tx) * 4 + g] = gm[u][g];
    }
    __syncthreads();
    if (tid < 128) {
        int c = tid;
        unsigned long long m = rpk[c * 16];
        float mg[4] = {rgm[c * 64 + 0], rgm[c * 64 + 1], rgm[c * 64 + 2], rgm[c * 64 + 3]};
#pragma unroll 1
        for (int t = 1; t < 16; t++) {
            unsigned long long q = rpk[c * 16 + t];
            if (q > m) m = q;
#pragma unroll
            for (int g = 0; g < 4; g++) mg[g] = fmaxf(mg[g], rgm[(c * 16 + t) * 4 + g]);
        }
        atomicMax(&g_pmax[b * 1024 + c0 + c], m);
#pragma unroll
        for (int g = 0; g < 4; g++)
            atomicMax(&g_gmax[g * 1024 + c0 + c], __float_as_uint(mg[g]));
    }
}

// ---------------- init + tail MLPs ----------------
__global__ void kInit() {
    int t = blockIdx.x * blockDim.x + threadIdx.x;
    if (t < BATCH * 1024) g_pmax[t] = 0ull;
    if (t < 4 * 1024) g_gmax[t] = 0u;
}

__global__ void kC1(const float* __restrict__ wg0, const float* __restrict__ bg0,
                    const float* __restrict__ wgr0, const float* __restrict__ bgr0,
                    float* __restrict__ out) {
    const int gtid = blockIdx.x * blockDim.x + threadIdx.x;
    // copy out max_indices (as floats) while we have g_pmax hot
    if (gtid < BATCH * 1024) {
        unsigned long long pv = g_pmax[gtid];
        out[4096 + gtid] = (float)(0xFFFFFFFFu - (unsigned int)(pv & 0xFFFFFFFFull));
    }
    const int wid = gtid >> 5;
    const int lane = gtid & 31;
    const int row = wid >> 9;   // 0..16
    const int j = wid & 511;
    if (row > 16) return;
    float s = 0.0f;
    if (row < 16) {
        const float* wr = wg0 + (size_t)j * 1024;
        const unsigned long long* pbuf = g_pmax + row * 1024;
        for (int k = lane; k < 1024; k += 32)
            s = fmaf(wr[k], __uint_as_float((unsigned int)(pbuf[k] >> 32)), s);
    } else {
        const float* wr = wgr0 + (size_t)j * 4096;
        for (int k = lane; k < 4096; k += 32)
            s = fmaf(wr[k], __uint_as_float(g_gmax[k]), s);
    }
#pragma unroll
    for (int o = 16; o; o >>= 1) s += __shfl_xor_sync(0xFFFFFFFFu, s, o);
    if (lane == 0) {
        float bb = (row < 16) ? bg0[j] : bgr0[j];
        g_u1[row * 512 + j] = fmaxf(s + bb, 0.0f);
    }
}

__global__ void kC2(const float* __restrict__ wg1, const float* __restrict__ bg1,
                    const float* __restrict__ wgr1, const float* __restrict__ bgr1,
                    float* __restrict__ out) {
    const int gtid = blockIdx.x * blockDim.x + threadIdx.x;
    const int wid = gtid >> 5;
    const int lane = gtid & 31;
    const int row = wid >> 7;   // 0..16
    const int j = wid & 127;
    if (row > 16) return;
    const float* wr = ((row < 16) ? wg1 : wgr1) + (size_t)j * 512;
    const float* in = g_u1 + row * 512;
    float s = 0.0f;
    for (int k = lane; k < 512; k += 32) s = fmaf(wr[k], in[k], s);
#pragma unroll
    for (int o = 16; o; o >>= 1) s += __shfl_xor_sync(0xFFFFFFFFu, s, o);
    s = __shfl_sync(0xFFFFFFFFu, s, 0);
    float bb = (row < 16) ? bg1[j] : bgr1[j];
    float val = fmaxf(s + bb, 0.0f);
    if (row < 16) {
        if (lane == 0) out[row * 256 + 128 + j] = val;  // output_feature half
    } else {
        if (lane < 16) out[lane * 256 + j] = val;       // group half, broadcast to all batches
    }
}

// ---------------- launch ----------------
extern "C" void kernel_launch(void* const* d_in, const int* in_sizes, int n_in,
                              void* d_out, int out_size) {
    const float* points = (const float*)d_in[0];
    const float* wl0 = (const float*)d_in[1];  const float* bl0 = (const float*)d_in[2];
    const float* wl1 = (const float*)d_in[3];  const float* bl1 = (const float*)d_in[4];
    const float* wl2 = (const float*)d_in[5];  const float* bl2 = (const float*)d_in[6];
    const float* wl3 = (const float*)d_in[7];  const float* bl3 = (const float*)d_in[8];
    const float* wl4 = (const float*)d_in[9];  const float* bl4 = (const float*)d_in[10];
    const float* wg0 = (const float*)d_in[11]; const float* bg0 = (const float*)d_in[12];
    const float* wg1 = (const float*)d_in[13]; const float* bg1 = (const float*)d_in[14];
    const float* wgr0 = (const float*)d_in[15]; const float* bgr0 = (const float*)d_in[16];
    const float* wgr1 = (const float*)d_in[17]; const float* bgr1 = (const float*)d_in[18];
    float* out = (float*)d_out;

    cudaFuncSetAttribute(kA, cudaFuncAttributeMaxDynamicSharedMemorySize,
                         KA_SMEM_FLOATS * (int)sizeof(float));
    cudaFuncSetAttribute(kB, cudaFuncAttributeMaxDynamicSharedMemorySize,
                         KB_SMEM_FLOATS * (int)sizeof(float));

    kInit<<<64, 256>>>();
    kA<<<(BATCH * NPTS) / 256, 256, KA_SMEM_FLOATS * sizeof(float)>>>(
        points, wl0, bl0, wl1, bl1, wl2, bl2, wl3, bl3);
    kB<<<1024, 256, KB_SMEM_FLOATS * sizeof(float)>>>(wl4, bl4);
    kC1<<<1088, 256>>>(wg0, bg0, wgr0, bgr0, out);
    kC2<<<272, 256>>>(wg1, bg1, wgr1, bgr1, out);
}